// round 2
// baseline (speedup 1.0000x reference)
#include <cuda_runtime.h>
#include <mma.h>
using namespace nvcuda;

#define NN 50000
#define F  64        // in feats
#define KK 256       // F * K(=4) = GEMM K dim
#define OF 256       // out feats

// ---- scratch (static __device__ arrays; no allocation allowed) ----
__device__ float g_dsq[NN];                 // deg accumulator, then rsqrt(max(deg,1))
__device__ float g_agg[NN * F];             // scatter destination
__device__ float g_Xt[(size_t)NN * KK];     // packed [X0 | X1 | X2 | X3]

// ---------------- degree ----------------
__global__ void zero_dsq_kernel() {
    int i = blockIdx.x * blockDim.x + threadIdx.x;
    if (i < NN) g_dsq[i] = 0.0f;
}

__global__ void deg_kernel(const int* __restrict__ dst, int E) {
    int e = blockIdx.x * blockDim.x + threadIdx.x;
    if (e < E) atomicAdd(&g_dsq[dst[e]], 1.0f);
}

__global__ void dsqrt_kernel() {
    int i = blockIdx.x * blockDim.x + threadIdx.x;
    if (i < NN) g_dsq[i] = rsqrtf(fmaxf(g_dsq[i], 1.0f));
}

// ---------------- init: X0 into Xt chunk0, zero agg ----------------
__global__ void init_kernel(const float* __restrict__ sig) {
    int i = blockIdx.x * blockDim.x + threadIdx.x;
    if (i >= NN * F) return;
    int row = i >> 6;
    int f   = i & 63;
    g_Xt[(size_t)row * KK + f] = sig[i];
    g_agg[i] = 0.0f;
}

// ---------------- edge scatter: agg[dst] += Xt[src,chunk]*dsq[src] ----------------
__global__ void scatter_kernel(const int* __restrict__ src,
                               const int* __restrict__ dst, int E, int in_off4) {
    int idx = blockIdx.x * blockDim.x + threadIdx.x;
    int e = idx >> 4;      // 16 threads per edge
    int j = idx & 15;      // which float4 of the 64-float row
    if (e >= E) return;
    int s = src[e];
    int d = dst[e];
    float ds = g_dsq[s];
    float4 v = ((const float4*)g_Xt)[(size_t)s * 64 + in_off4 + j];
    v.x *= ds; v.y *= ds; v.z *= ds; v.w *= ds;
    float* p = g_agg + (size_t)d * F + j * 4;
    asm volatile("red.global.add.v4.f32 [%0], {%1,%2,%3,%4};"
                 :: "l"(p), "f"(v.x), "f"(v.y), "f"(v.z), "f"(v.w)
                 : "memory");
}

// ---------------- Chebyshev combine (also re-zeroes agg for next pass) ----------------
// step==1: X1 = -r*L + (r-1)*X0
// step>=2: Xk = -2r*L + 2(r-1)*X_{k-1} - X_{k-2}
__global__ void combine_kernel(const float* __restrict__ lam,
                               int out_off, int p1_off, int p2_off,
                               int step) {
    int i = blockIdx.x * blockDim.x + threadIdx.x;
    if (i >= NN * F) return;
    float r = 2.0f / lam[0];
    int row = i >> 6;
    int f   = i & 63;
    float ds = g_dsq[row];
    float L  = g_agg[i] * ds;
    g_agg[i] = 0.0f;                       // ready for next scatter pass
    const float* base = g_Xt + (size_t)row * KK + f;
    float out;
    if (step == 1) {
        out = -r * L + (r - 1.0f) * base[p1_off];
    } else {
        out = -2.0f * r * L + 2.0f * (r - 1.0f) * base[p1_off] - base[p2_off];
    }
    g_Xt[(size_t)row * KK + out_off + f] = out;
}

// ---------------- tf32 tensor-core GEMM + bias + ReLU ----------------
// C[M, OF] = relu(Xt[M, KK] @ W[KK, OF] + b)
#define GBM 128
#define GBN 128
#define GBK 32
#define APAD 8
#define BPAD 8

__global__ __launch_bounds__(256)
void gemm_tf32(const float* __restrict__ W, const float* __restrict__ bias,
               float* __restrict__ C, int M) {
    __shared__ float As[GBM][GBK + APAD];   // 128 x 40   (20.5 KB)
    __shared__ float Bs[GBK][GBN + BPAD];   // 32 x 136   (17.4 KB)
    __shared__ float Cst[8][16 * 16];       // per-warp epilogue staging (8 KB)

    int bx = blockIdx.x, by = blockIdx.y;
    int tid = threadIdx.x;
    int warp = tid >> 5, lane = tid & 31;
    int wm = warp >> 2;   // 0..1 : 64-row slab
    int wn = warp & 3;    // 0..3 : 32-col slab

    wmma::fragment<wmma::accumulator, 16, 16, 8, float> acc[4][2];
#pragma unroll
    for (int i = 0; i < 4; i++)
#pragma unroll
        for (int j = 0; j < 2; j++) wmma::fill_fragment(acc[i][j], 0.0f);

    for (int k0 = 0; k0 < KK; k0 += GBK) {
        // A tile: 128 rows x 32 cols (8 float4/row -> 1024 float4, 4/thread)
#pragma unroll
        for (int it = 0; it < 4; it++) {
            int fl = tid + it * 256;
            int row = fl >> 3;
            int col = (fl & 7) * 4;
            int gr = by * GBM + row;
            float4 v = make_float4(0.f, 0.f, 0.f, 0.f);
            if (gr < M) v = *(const float4*)(g_Xt + (size_t)gr * KK + k0 + col);
            *(float4*)&As[row][col] = v;
        }
        // B tile: 32 rows x 128 cols (32 float4/row -> 1024 float4, 4/thread)
#pragma unroll
        for (int it = 0; it < 4; it++) {
            int fl = tid + it * 256;
            int row = fl >> 5;
            int col = (fl & 31) * 4;
            float4 v = *(const float4*)(W + (size_t)(k0 + row) * OF + bx * GBN + col);
            *(float4*)&Bs[row][col] = v;
        }
        __syncthreads();

#pragma unroll
        for (int kk = 0; kk < GBK; kk += 8) {
            wmma::fragment<wmma::matrix_a, 16, 16, 8, wmma::precision::tf32, wmma::row_major> af[4];
            wmma::fragment<wmma::matrix_b, 16, 16, 8, wmma::precision::tf32, wmma::row_major> bf[2];
#pragma unroll
            for (int i = 0; i < 4; i++) {
                wmma::load_matrix_sync(af[i], &As[wm * 64 + i * 16][kk], GBK + APAD);
#pragma unroll
                for (int t = 0; t < af[i].num_elements; t++)
                    af[i].x[t] = wmma::__float_to_tf32(af[i].x[t]);
            }
#pragma unroll
            for (int j = 0; j < 2; j++) {
                wmma::load_matrix_sync(bf[j], &Bs[kk][wn * 32 + j * 16], GBN + BPAD);
#pragma unroll
                for (int t = 0; t < bf[j].num_elements; t++)
                    bf[j].x[t] = wmma::__float_to_tf32(bf[j].x[t]);
            }
#pragma unroll
            for (int i = 0; i < 4; i++)
#pragma unroll
                for (int j = 0; j < 2; j++)
                    wmma::mma_sync(acc[i][j], af[i], bf[j], acc[i][j]);
        }
        __syncthreads();
    }

    // epilogue: stage each 16x16 frag through smem, add bias + relu, vec store
#pragma unroll
    for (int i = 0; i < 4; i++) {
#pragma unroll
        for (int j = 0; j < 2; j++) {
            wmma::store_matrix_sync(Cst[warp], acc[i][j], 16, wmma::mem_row_major);
            __syncwarp();
            int r0 = by * GBM + wm * 64 + i * 16;
            int c0 = bx * GBN + wn * 32 + j * 16;
            int lr = lane >> 1;            // 0..15
            int lc = (lane & 1) * 8;       // 0 or 8
            int row = r0 + lr;
            if (row < M) {
#pragma unroll
                for (int c = 0; c < 8; c += 4) {
                    int col = c0 + lc + c;
                    float4 o;
                    o.x = fmaxf(Cst[warp][lr * 16 + lc + c + 0] + bias[col + 0], 0.0f);
                    o.y = fmaxf(Cst[warp][lr * 16 + lc + c + 1] + bias[col + 1], 0.0f);
                    o.z = fmaxf(Cst[warp][lr * 16 + lc + c + 2] + bias[col + 2], 0.0f);
                    o.w = fmaxf(Cst[warp][lr * 16 + lc + c + 3] + bias[col + 3], 0.0f);
                    *(float4*)(C + (size_t)row * OF + col) = o;
                }
            }
            __syncwarp();
        }
    }
}

// ---------------- launch ----------------
extern "C" void kernel_launch(void* const* d_in, const int* in_sizes, int n_in,
                              void* d_out, int out_size) {
    const float* signal = (const float*)d_in[0];
    const int*   src    = (const int*)d_in[1];
    const int*   dst    = (const int*)d_in[2];
    const float* lam    = (const float*)d_in[3];
    const float* W      = (const float*)d_in[4];
    const float* b      = (const float*)d_in[5];
    float* out = (float*)d_out;

    const int E = in_sizes[1];
    const int NFB = (NN * F + 255) / 256;     // node-feature grid
    const int EB  = (E + 255) / 256;
    const int SB  = (E * 16 + 255) / 256;     // scatter grid (16 thr/edge)

    // degrees
    zero_dsq_kernel<<<(NN + 255) / 256, 256>>>();
    deg_kernel<<<EB, 256>>>(dst, E);
    dsqrt_kernel<<<(NN + 255) / 256, 256>>>();

    // X0 + zero agg
    init_kernel<<<NFB, 256>>>(signal);

    // X1  (scatter reads Xt chunk 0 scaled by dsq inline)
    scatter_kernel<<<SB, 256>>>(src, dst, E, /*in_off4*/0);
    combine_kernel<<<NFB, 256>>>(lam, /*out*/64, /*p1*/0, /*p2*/0, 1);

    // X2
    scatter_kernel<<<SB, 256>>>(src, dst, E, /*in_off4*/16);
    combine_kernel<<<NFB, 256>>>(lam, /*out*/128, /*p1*/64, /*p2*/0, 2);

    // X3
    scatter_kernel<<<SB, 256>>>(src, dst, E, /*in_off4*/32);
    combine_kernel<<<NFB, 256>>>(lam, /*out*/192, /*p1*/128, /*p2*/64, 2);

    // out = relu(Xt @ W + b)   -- tf32 tensor cores
    dim3 grid(OF / GBN, (NN + GBM - 1) / GBM);
    gemm_tf32<<<grid, 256>>>(W, b, out, NN);
}

// round 5
// speedup vs baseline: 1.5101x; 1.5101x over previous
#include <cuda_runtime.h>
#include <mma.h>
using namespace nvcuda;

#define NN 50000
#define F  64        // in feats
#define KK 256       // F * K(=4) = GEMM K dim
#define OF 256       // out feats
#define EE 800000

// ---- scratch (static __device__ arrays; no allocation allowed) ----
__device__ float g_dsq[NN];                 // deg accumulator -> rsqrt(max(deg,1))
__device__ int   g_rowptr[NN + 1];          // CSR row pointers (in-edges by dst)
__device__ int   g_fill[NN];                // fill counters
__device__ int   g_col[EE];                 // CSR column (src node of each in-edge)
__device__ float g_Xt[(size_t)NN * KK];     // packed [X0 | X1 | X2 | X3]

// ---------------- degree ----------------
__global__ void zero_dsq_kernel() {
    int i = blockIdx.x * blockDim.x + threadIdx.x;
    if (i < NN) g_dsq[i] = 0.0f;
}

__global__ void deg_kernel(const int* __restrict__ dst, int E) {
    int e = blockIdx.x * blockDim.x + threadIdx.x;
    if (e < E) atomicAdd(&g_dsq[dst[e]], 1.0f);
}

// scan raw float degrees -> exclusive rowptr; zero fill counters
__global__ __launch_bounds__(1024)
void scan_kernel() {
    __shared__ int part[1024];
    int t = threadIdx.x;
    const int CH = (NN + 1023) / 1024;   // 49
    int base = t * CH;
    int s = 0;
#pragma unroll 4
    for (int i = 0; i < CH; i++) {
        int idx = base + i;
        if (idx < NN) s += (int)g_dsq[idx];
    }
    part[t] = s;
    __syncthreads();
    for (int off = 1; off < 1024; off <<= 1) {
        int v = 0;
        if (t >= off) v = part[t - off];
        __syncthreads();
        if (t >= off) part[t] += v;
        __syncthreads();
    }
    int run = part[t] - s;   // exclusive prefix at chunk start
    for (int i = 0; i < CH; i++) {
        int idx = base + i;
        if (idx < NN) {
            g_rowptr[idx] = run;
            run += (int)g_dsq[idx];
            g_fill[idx] = 0;
        }
    }
    if (t == 1023) g_rowptr[NN] = run;
}

__global__ void dsqrt_kernel() {
    int i = blockIdx.x * blockDim.x + threadIdx.x;
    if (i < NN) g_dsq[i] = rsqrtf(fmaxf(g_dsq[i], 1.0f));
}

__global__ void fill_kernel(const int* __restrict__ src,
                            const int* __restrict__ dst, int E) {
    int e = blockIdx.x * blockDim.x + threadIdx.x;
    if (e >= E) return;
    int d = dst[e];
    int pos = g_rowptr[d] + atomicAdd(&g_fill[d], 1);
    g_col[pos] = src[e];
}

// ---------------- init: X0 into Xt chunk0 ----------------
__global__ void init_kernel(const float* __restrict__ sig) {
    int i = blockIdx.x * blockDim.x + threadIdx.x;
    if (i >= NN * (F / 4)) return;          // float4 granularity
    int row = i >> 4;
    int c4  = i & 15;
    float4 v = ((const float4*)sig)[i];
    ((float4*)(g_Xt + (size_t)row * KK))[c4] = v;
}

// ---------------- fused Chebyshev step: gather + combine, no atomics ----------------
// warp per node v:
//   agg = sum_{in-edges} dsq[src] * Xt[src, in_chunk]
//   L = dsq[v] * agg
//   step 1: out = -r*L + (r-1)*X_p1
//   step 2: out = -2r*L + 2(r-1)*X_p1 - X_p2
__global__ __launch_bounds__(256)
void cheb_step_kernel(const float* __restrict__ lam,
                      int in_off, int out_off, int p1_off, int p2_off, int step) {
    int gtid = blockIdx.x * blockDim.x + threadIdx.x;
    int v = gtid >> 5;
    int lane = gtid & 31;
    if (v >= NN) return;

    int p   = g_rowptr[v];
    int end = g_rowptr[v + 1];
    float ax = 0.0f, ay = 0.0f;

    for (; p + 1 < end; p += 2) {
        int s0 = g_col[p];
        int s1 = g_col[p + 1];
        float d0 = g_dsq[s0];
        float d1 = g_dsq[s1];
        float2 x0 = *(const float2*)(g_Xt + (size_t)s0 * KK + in_off + lane * 2);
        float2 x1 = *(const float2*)(g_Xt + (size_t)s1 * KK + in_off + lane * 2);
        ax += d0 * x0.x + d1 * x1.x;
        ay += d0 * x0.y + d1 * x1.y;
    }
    if (p < end) {
        int s0 = g_col[p];
        float d0 = g_dsq[s0];
        float2 x0 = *(const float2*)(g_Xt + (size_t)s0 * KK + in_off + lane * 2);
        ax += d0 * x0.x;
        ay += d0 * x0.y;
    }

    float dsv = g_dsq[v];
    float r = 2.0f / lam[0];
    float Lx = ax * dsv, Ly = ay * dsv;

    const float* base = g_Xt + (size_t)v * KK + lane * 2;
    float2 p1 = *(const float2*)(base + p1_off);
    float2 out;
    if (step == 1) {
        out.x = -r * Lx + (r - 1.0f) * p1.x;
        out.y = -r * Ly + (r - 1.0f) * p1.y;
    } else {
        float2 p2 = *(const float2*)(base + p2_off);
        out.x = -2.0f * r * Lx + 2.0f * (r - 1.0f) * p1.x - p2.x;
        out.y = -2.0f * r * Ly + 2.0f * (r - 1.0f) * p1.y - p2.y;
    }
    *(float2*)(g_Xt + (size_t)v * KK + out_off + lane * 2) = out;
}

// ---------------- pipelined tf32 tensor-core GEMM + bias + ReLU ----------------
// C[M, OF] = relu(Xt[M, KK] @ W[KK, OF] + b)
#define GBM 128
#define GBN 128
#define GBK 16
#define AROW 28                    // padded floats per A row (16 + 12)
#define BROW 140                   // padded floats per B row (128 + 12)
#define ASTG (GBM * AROW)          // 3584
#define STG  (ASTG + GBK * BROW)   // 3584 + 2240 = 5824 floats / stage

__device__ __forceinline__ void cp16(float* dstp, const float* src, int sz) {
    unsigned saddr = (unsigned)__cvta_generic_to_shared(dstp);
    asm volatile("cp.async.ca.shared.global [%0], [%1], 16, %2;"
                 :: "r"(saddr), "l"(src), "r"(sz));
}

__global__ __launch_bounds__(256)
void gemm_tf32(const float* __restrict__ W, const float* __restrict__ bias,
               float* __restrict__ C, int M) {
    __shared__ float sm[2 * STG];   // 46.6 KB

    int bx = blockIdx.x, by = blockIdx.y;
    int tid = threadIdx.x;
    int warp = tid >> 5, lane = tid & 31;
    int wm = warp >> 2;   // 0..1 : 64-row slab
    int wn = warp & 3;    // 0..3 : 32-col slab

    wmma::fragment<wmma::accumulator, 16, 16, 8, float> acc[4][2];
#pragma unroll
    for (int i = 0; i < 4; i++)
#pragma unroll
        for (int j = 0; j < 2; j++) wmma::fill_fragment(acc[i][j], 0.0f);

    const int NT = KK / GBK;   // 16 stages

    // async stage loader (OOB rows: clamp pointer, src-size 0 -> zero-fill)
    auto load_stage = [&](int t, int stg) {
        float* s = sm + stg * STG;
        int k0 = t * GBK;
#pragma unroll
        for (int it = 0; it < 2; it++) {            // A: 512 float4
            int idx = tid + it * 256;
            int row = idx >> 2, c4 = idx & 3;
            int gr = by * GBM + row;
            int grc = (gr < M) ? gr : (M - 1);      // clamped, always valid
            const float* srcp = g_Xt + (size_t)grc * KK + k0 + c4 * 4;
            cp16(s + row * AROW + c4 * 4, srcp, (gr < M) ? 16 : 0);
        }
#pragma unroll
        for (int it = 0; it < 2; it++) {            // B: 512 float4
            int idx = tid + it * 256;
            int row = idx >> 5, c4 = idx & 31;
            const float* srcp = W + (size_t)(k0 + row) * OF + bx * GBN + c4 * 4;
            cp16(s + ASTG + row * BROW + c4 * 4, srcp, 16);
        }
        asm volatile("cp.async.commit_group;");
    };

    load_stage(0, 0);

    for (int t = 0; t < NT; t++) {
        if (t + 1 < NT) {
            load_stage(t + 1, (t + 1) & 1);
            asm volatile("cp.async.wait_group 1;");
        } else {
            asm volatile("cp.async.wait_group 0;");
        }
        __syncthreads();

        const float* s = sm + (t & 1) * STG;
#pragma unroll
        for (int kk = 0; kk < GBK; kk += 8) {
            wmma::fragment<wmma::matrix_a, 16, 16, 8, wmma::precision::tf32, wmma::row_major> af[4];
            wmma::fragment<wmma::matrix_b, 16, 16, 8, wmma::precision::tf32, wmma::row_major> bf[2];
#pragma unroll
            for (int i = 0; i < 4; i++) {
                wmma::load_matrix_sync(af[i], s + (wm * 64 + i * 16) * AROW + kk, AROW);
#pragma unroll
                for (int e = 0; e < af[i].num_elements; e++)
                    af[i].x[e] = wmma::__float_to_tf32(af[i].x[e]);
            }
#pragma unroll
            for (int j = 0; j < 2; j++) {
                wmma::load_matrix_sync(bf[j], s + ASTG + kk * BROW + wn * 32 + j * 16, BROW);
#pragma unroll
                for (int e = 0; e < bf[j].num_elements; e++)
                    bf[j].x[e] = wmma::__float_to_tf32(bf[j].x[e]);
            }
#pragma unroll
            for (int i = 0; i < 4; i++)
#pragma unroll
                for (int j = 0; j < 2; j++)
                    wmma::mma_sync(acc[i][j], af[i], bf[j], acc[i][j]);
        }
        __syncthreads();
    }

    // epilogue: stage fragments through (reused) smem, add bias + relu
    float* Cw = sm + warp * 256;
#pragma unroll
    for (int i = 0; i < 4; i++) {
#pragma unroll
        for (int j = 0; j < 2; j++) {
            wmma::store_matrix_sync(Cw, acc[i][j], 16, wmma::mem_row_major);
            __syncwarp();
            int r0 = by * GBM + wm * 64 + i * 16;
            int c0 = bx * GBN + wn * 32 + j * 16;
            int lr = lane >> 1;
            int lc = (lane & 1) * 8;
            int row = r0 + lr;
            if (row < M) {
#pragma unroll
                for (int c = 0; c < 8; c += 4) {
                    int col = c0 + lc + c;
                    float4 o;
                    o.x = fmaxf(Cw[lr * 16 + lc + c + 0] + bias[col + 0], 0.0f);
                    o.y = fmaxf(Cw[lr * 16 + lc + c + 1] + bias[col + 1], 0.0f);
                    o.z = fmaxf(Cw[lr * 16 + lc + c + 2] + bias[col + 2], 0.0f);
                    o.w = fmaxf(Cw[lr * 16 + lc + c + 3] + bias[col + 3], 0.0f);
                    *(float4*)(C + (size_t)row * OF + col) = o;
                }
            }
            __syncwarp();
        }
    }
}

// ---------------- launch ----------------
extern "C" void kernel_launch(void* const* d_in, const int* in_sizes, int n_in,
                              void* d_out, int out_size) {
    const float* signal = (const float*)d_in[0];
    const int*   src    = (const int*)d_in[1];
    const int*   dst    = (const int*)d_in[2];
    const float* lam    = (const float*)d_in[3];
    const float* W      = (const float*)d_in[4];
    const float* b      = (const float*)d_in[5];
    float* out = (float*)d_out;

    const int E = in_sizes[1];
    const int EB = (E + 255) / 256;

    // degrees + CSR
    zero_dsq_kernel<<<(NN + 255) / 256, 256>>>();
    deg_kernel<<<EB, 256>>>(dst, E);
    scan_kernel<<<1, 1024>>>();
    dsqrt_kernel<<<(NN + 255) / 256, 256>>>();
    fill_kernel<<<EB, 256>>>(src, dst, E);

    // X0
    init_kernel<<<(NN * 16 + 255) / 256, 256>>>(signal);

    // Chebyshev passes (warp per node, fused gather+combine)
    const int CB = (NN * 32 + 255) / 256;   // 6250 blocks
    cheb_step_kernel<<<CB, 256>>>(lam, /*in*/0,   /*out*/64,  /*p1*/0,   /*p2*/0,  1);
    cheb_step_kernel<<<CB, 256>>>(lam, /*in*/64,  /*out*/128, /*p1*/64,  /*p2*/0,  2);
    cheb_step_kernel<<<CB, 256>>>(lam, /*in*/128, /*out*/192, /*p1*/128, /*p2*/64, 2);

    // out = relu(Xt @ W + b)  -- pipelined tf32 tensor cores
    dim3 grid(OF / GBN, (NN + GBM - 1) / GBM);
    gemm_tf32<<<grid, 256>>>(W, b, out, NN);
}